// round 15
// baseline (speedup 1.0000x reference)
#include <cuda_runtime.h>
#include <cstdint>

#define N_MAX 100000
#define E_CONST 640000
#define FIN 128
#define F1 128
#define F2 64

// ---------------- device-resident scratch ----------------
// RULE: referenced ONLY inside device code (host-taken addresses of __device__
// symbols resolve to the ATS host shadow on GB300 -> 3ms C2C penalty).
// g_cnt invariant: zero at every kernel_launch entry (load-time zero-init;
// k_scan_all resets it to zero after consuming it each call).
__device__ __align__(128) float g_dinv[N_MAX];
__device__ __align__(128) float g_h1[(size_t)N_MAX * F1];
__device__ __align__(128) float g_y1[(size_t)N_MAX * F1];
__device__ __align__(128) float g_h2[(size_t)N_MAX * F2];
__device__ int g_cnt[N_MAX];
__device__ int g_rowptr[N_MAX + 1];
__device__ int g_woff[N_MAX];
__device__ int g_csrc[E_CONST];

// ---------------- degree count (precondition: g_cnt == 0) ----------------
__global__ void k_count(const int* __restrict__ edge, int e) {
    int i = blockIdx.x * blockDim.x + threadIdx.x;
    if (i < e) atomicAdd(&g_cnt[edge[e + i]], 1);  // dst
}

// ---------------- fused scan: rowptr + woff + dinv + cnt-reset, ONE block ------
__global__ void __launch_bounds__(1024) k_scan_all(int n) {
    __shared__ int sm[1024];
    const int t = threadIdx.x;
    const int chunk = (n + 1023) >> 10;
    const int beg = t * chunk;
    const int end = (beg + chunk < n) ? beg + chunk : n;

    int sum = 0;
    for (int i = beg; i < end; i++) sum += g_cnt[i];
    sm[t] = sum;
    __syncthreads();
    #pragma unroll
    for (int off = 1; off < 1024; off <<= 1) {
        int x = sm[t];
        if (t >= off) x += sm[t - off];
        __syncthreads();
        sm[t] = x;
        __syncthreads();
    }
    int run = (t > 0) ? sm[t - 1] : 0;  // exclusive prefix of this chunk
    for (int i = beg; i < end; i++) {
        int c = g_cnt[i];
        g_cnt[i] = 0;                    // restore invariant for next call
        g_woff[i] = run;
        run += c;
        g_rowptr[i + 1] = run;
        g_dinv[i] = rsqrtf(1.0f + (float)c);
    }
    if (t == 0) g_rowptr[0] = 0;
}

__global__ void k_fill(const int* __restrict__ edge, int e) {
    int i = blockIdx.x * blockDim.x + threadIdx.x;
    if (i < e) {
        int d = edge[e + i];
        int pos = atomicAdd(&g_woff[d], 1);
        g_csrc[pos] = edge[i];
    }
}

// ---------------- tiled GEMM body ----------------
template <int FOUT>
__device__ __forceinline__ void gemm_body(const float* __restrict__ X,
                                          const float* __restrict__ W,
                                          float* __restrict__ h, int n) {
    __shared__ float Xs[32 * FIN];
    __shared__ float Ws[FIN * 64];
    const int tid = threadIdx.x;
    const int row0 = blockIdx.x * 32;
    const int colbase = blockIdx.y * 64;

    for (int i = tid; i < 32 * FIN / 4; i += 256) {
        int r = i >> 5;
        int c4 = i & 31;
        int gr = row0 + r;
        float4 v = make_float4(0.f, 0.f, 0.f, 0.f);
        if (gr < n) v = *(const float4*)(X + (size_t)gr * FIN + c4 * 4);
        *(float4*)(Xs + r * FIN + c4 * 4) = v;
    }
    for (int i = tid; i < FIN * 64 / 4; i += 256) {
        int k = i >> 4;
        int c4 = i & 15;
        *(float4*)(Ws + k * 64 + c4 * 4) =
            *(const float4*)(W + (size_t)k * FOUT + colbase + c4 * 4);
    }
    __syncthreads();

    const int tx = tid & 31;
    const int ty = tid >> 5;

    float acc[4][2];
    #pragma unroll
    for (int r = 0; r < 4; r++) { acc[r][0] = 0.f; acc[r][1] = 0.f; }

    for (int k0 = 0; k0 < FIN; k0 += 4) {
        float4 xv[4];
        #pragma unroll
        for (int r = 0; r < 4; r++)
            xv[r] = *(const float4*)(Xs + (ty * 4 + r) * FIN + k0);
        #pragma unroll
        for (int kk = 0; kk < 4; kk++) {
            float w0 = Ws[(k0 + kk) * 64 + tx];
            float w1 = Ws[(k0 + kk) * 64 + tx + 32];
            #pragma unroll
            for (int r = 0; r < 4; r++) {
                float xe = (kk == 0) ? xv[r].x : (kk == 1) ? xv[r].y
                         : (kk == 2) ? xv[r].z : xv[r].w;
                acc[r][0] = fmaf(xe, w0, acc[r][0]);
                acc[r][1] = fmaf(xe, w1, acc[r][1]);
            }
        }
    }

    #pragma unroll
    for (int r = 0; r < 4; r++) {
        int gr = row0 + ty * 4 + r;
        if (gr < n) {
            h[(size_t)gr * FOUT + colbase + tx]      = acc[r][0];
            h[(size_t)gr * FOUT + colbase + tx + 32] = acc[r][1];
        }
    }
}

__global__ void __launch_bounds__(256) k_gemm1(const float* __restrict__ x,
                                               const float* __restrict__ W1, int n) {
    gemm_body<F1>(x, W1, g_h1, n);
}
__global__ void __launch_bounds__(256) k_gemm2(const float* __restrict__ W2, int n) {
    gemm_body<F2>(g_y1, W2, g_h2, n);
}

// ---------------- fused CSR aggregation ----------------
__global__ void k_agg_relu(const float* __restrict__ b, int n) {
    int node = (blockIdx.x * blockDim.x + threadIdx.x) >> 5;
    int lane = threadIdx.x & 31;
    if (node >= n) return;
    float dv = g_dinv[node];

    float4 acc = *(const float4*)(g_h1 + (size_t)node * F1 + lane * 4);
    acc.x *= dv; acc.y *= dv; acc.z *= dv; acc.w *= dv;

    int beg = g_rowptr[node], end = g_rowptr[node + 1];
    int i = beg;
    for (; i + 4 <= end; i += 4) {
        int s0 = g_csrc[i], s1 = g_csrc[i + 1], s2 = g_csrc[i + 2], s3 = g_csrc[i + 3];
        float w0 = g_dinv[s0], w1 = g_dinv[s1], w2 = g_dinv[s2], w3 = g_dinv[s3];
        float4 v0 = *(const float4*)(g_h1 + (size_t)s0 * F1 + lane * 4);
        float4 v1 = *(const float4*)(g_h1 + (size_t)s1 * F1 + lane * 4);
        float4 v2 = *(const float4*)(g_h1 + (size_t)s2 * F1 + lane * 4);
        float4 v3 = *(const float4*)(g_h1 + (size_t)s3 * F1 + lane * 4);
        acc.x = fmaf(w0, v0.x, fmaf(w1, v1.x, fmaf(w2, v2.x, fmaf(w3, v3.x, acc.x))));
        acc.y = fmaf(w0, v0.y, fmaf(w1, v1.y, fmaf(w2, v2.y, fmaf(w3, v3.y, acc.y))));
        acc.z = fmaf(w0, v0.z, fmaf(w1, v1.z, fmaf(w2, v2.z, fmaf(w3, v3.z, acc.z))));
        acc.w = fmaf(w0, v0.w, fmaf(w1, v1.w, fmaf(w2, v2.w, fmaf(w3, v3.w, acc.w))));
    }
    for (; i < end; i++) {
        int s = g_csrc[i];
        float w = g_dinv[s];
        float4 v = *(const float4*)(g_h1 + (size_t)s * F1 + lane * 4);
        acc.x = fmaf(w, v.x, acc.x);
        acc.y = fmaf(w, v.y, acc.y);
        acc.z = fmaf(w, v.z, acc.z);
        acc.w = fmaf(w, v.w, acc.w);
    }

    float4 bb = *(const float4*)(b + lane * 4);
    float4 o;
    o.x = fmaxf(fmaf(acc.x, dv, bb.x), 0.f);
    o.y = fmaxf(fmaf(acc.y, dv, bb.y), 0.f);
    o.z = fmaxf(fmaf(acc.z, dv, bb.z), 0.f);
    o.w = fmaxf(fmaf(acc.w, dv, bb.w), 0.f);
    *(float4*)(g_y1 + (size_t)node * F1 + lane * 4) = o;
}

__global__ void k_agg_lsm(const float* __restrict__ b, float* __restrict__ out, int n) {
    int node = (blockIdx.x * blockDim.x + threadIdx.x) >> 5;
    int lane = threadIdx.x & 31;
    if (node >= n) return;
    float dv = g_dinv[node];

    float2 acc = *(const float2*)(g_h2 + (size_t)node * F2 + lane * 2);
    acc.x *= dv; acc.y *= dv;

    int beg = g_rowptr[node], end = g_rowptr[node + 1];
    int i = beg;
    for (; i + 4 <= end; i += 4) {
        int s0 = g_csrc[i], s1 = g_csrc[i + 1], s2 = g_csrc[i + 2], s3 = g_csrc[i + 3];
        float w0 = g_dinv[s0], w1 = g_dinv[s1], w2 = g_dinv[s2], w3 = g_dinv[s3];
        float2 v0 = *(const float2*)(g_h2 + (size_t)s0 * F2 + lane * 2);
        float2 v1 = *(const float2*)(g_h2 + (size_t)s1 * F2 + lane * 2);
        float2 v2 = *(const float2*)(g_h2 + (size_t)s2 * F2 + lane * 2);
        float2 v3 = *(const float2*)(g_h2 + (size_t)s3 * F2 + lane * 2);
        acc.x = fmaf(w0, v0.x, fmaf(w1, v1.x, fmaf(w2, v2.x, fmaf(w3, v3.x, acc.x))));
        acc.y = fmaf(w0, v0.y, fmaf(w1, v1.y, fmaf(w2, v2.y, fmaf(w3, v3.y, acc.y))));
    }
    for (; i < end; i++) {
        int s = g_csrc[i];
        float w = g_dinv[s];
        float2 v = *(const float2*)(g_h2 + (size_t)s * F2 + lane * 2);
        acc.x = fmaf(w, v.x, acc.x);
        acc.y = fmaf(w, v.y, acc.y);
    }

    float2 bb = *(const float2*)(b + lane * 2);
    float v0 = fmaf(acc.x, dv, bb.x);
    float v1 = fmaf(acc.y, dv, bb.y);
    float m = fmaxf(v0, v1);
    #pragma unroll
    for (int o = 16; o; o >>= 1) m = fmaxf(m, __shfl_xor_sync(0xffffffffu, m, o));
    float s = expf(v0 - m) + expf(v1 - m);
    #pragma unroll
    for (int o = 16; o; o >>= 1) s += __shfl_xor_sync(0xffffffffu, s, o);
    float lse = m + logf(s);
    float2 o2 = make_float2(v0 - lse, v1 - lse);
    *(float2*)(out + (size_t)node * F2 + lane * 2) = o2;
}

// ---------------- launch: single stream, straight-line graph ----------------
extern "C" void kernel_launch(void* const* d_in, const int* in_sizes, int n_in,
                              void* d_out, int out_size) {
    const float* x  = (const float*)d_in[0];
    const int* edge = (const int*)d_in[1];   // int32 [2, E]
    const float* W1 = (const float*)d_in[2];
    const float* b1 = (const float*)d_in[3];
    const float* W2 = (const float*)d_in[4];
    const float* b2 = (const float*)d_in[5];
    float* out = (float*)d_out;

    const int n = in_sizes[0] / FIN;  // 100000
    const int e = E_CONST;            // 640000
    const int T = 256;
    const long long aggth = (long long)n * 32;
    const int aggblk = (int)((aggth + T - 1) / T);
    const dim3 grid1((n + 31) / 32, F1 / 64);
    const dim3 grid2((n + 31) / 32, F2 / 64);

    k_count<<<(e + T - 1) / T, T>>>(edge, e);
    k_scan_all<<<1, 1024>>>(n);
    k_fill<<<(e + T - 1) / T, T>>>(edge, e);

    k_gemm1<<<grid1, T>>>(x, W1, n);
    k_agg_relu<<<aggblk, T>>>(b1, n);

    k_gemm2<<<grid2, T>>>(W2, n);
    k_agg_lsm<<<aggblk, T>>>(b2, out, n);
}

// round 16
// speedup vs baseline: 2.0654x; 2.0654x over previous
#include <cuda_runtime.h>
#include <cstdint>

#define N_MAX 100000
#define E_CONST 640000
#define FIN 128
#define F1 128
#define F2 64
#define SCAN_B 1024
#define MAX_BLKS 128

// ---------------- device-resident scratch ----------------
// RULE: referenced ONLY inside device code (host-taken addresses of __device__
// symbols resolve to the ATS host shadow on GB300 -> 3ms C2C penalty).
__device__ __align__(128) float g_dinv[N_MAX];
__device__ __align__(128) float g_h1[(size_t)N_MAX * F1];
__device__ __align__(128) float g_y1[(size_t)N_MAX * F1];
__device__ __align__(128) float g_h2[(size_t)N_MAX * F2];
__device__ int g_cnt[N_MAX];
__device__ int g_partial[N_MAX];
__device__ int g_bsum[MAX_BLKS];
__device__ int g_bpref[MAX_BLKS];
__device__ int g_rowptr[N_MAX + 1];
__device__ int g_woff[N_MAX];
__device__ int g_csrc[E_CONST];

// ---------------- CSR build (R13 proven version: coalesced, multi-SM) ----------------
__global__ void k_zero_cnt(int n) {
    int i = blockIdx.x * blockDim.x + threadIdx.x;
    if (i < n) g_cnt[i] = 0;
}

__global__ void k_count(const int* __restrict__ edge, int e) {
    int i = blockIdx.x * blockDim.x + threadIdx.x;
    if (i < e) atomicAdd(&g_cnt[edge[e + i]], 1);  // dst
}

__global__ void k_scan1(int n) {
    __shared__ int sm[SCAN_B];
    int t = threadIdx.x;
    int i = blockIdx.x * SCAN_B + t;
    sm[t] = (i < n) ? g_cnt[i] : 0;
    __syncthreads();
    for (int off = 1; off < SCAN_B; off <<= 1) {
        int x = sm[t];
        if (t >= off) x += sm[t - off];
        __syncthreads();
        sm[t] = x;
        __syncthreads();
    }
    if (i < n) g_partial[i] = sm[t];
    if (t == SCAN_B - 1) g_bsum[blockIdx.x] = sm[t];
}

__global__ void k_scan2(int nblk) {
    __shared__ int sm[MAX_BLKS];
    int t = threadIdx.x;
    sm[t] = (t < nblk) ? g_bsum[t] : 0;
    __syncthreads();
    for (int off = 1; off < MAX_BLKS; off <<= 1) {
        int x = sm[t];
        if (t >= off) x += sm[t - off];
        __syncthreads();
        sm[t] = x;
        __syncthreads();
    }
    g_bpref[t] = sm[t];
}

__global__ void k_scan3(int n) {
    int i = blockIdx.x * blockDim.x + threadIdx.x;
    if (i < n) {
        int c = g_cnt[i];
        int b = i >> 10;
        int off = (b > 0) ? g_bpref[b - 1] : 0;
        int incl = g_partial[i] + off;
        g_rowptr[i + 1] = incl;
        g_woff[i] = incl - c;
        g_dinv[i] = rsqrtf(1.0f + (float)c);
    }
    if (i == 0) g_rowptr[0] = 0;
}

__global__ void k_fill(const int* __restrict__ edge, int e) {
    int i = blockIdx.x * blockDim.x + threadIdx.x;
    if (i < e) {
        int d = edge[e + i];
        int pos = atomicAdd(&g_woff[d], 1);
        g_csrc[pos] = edge[i];
    }
}

// ---------------- tf32 tensor-core GEMM ----------------
__device__ __forceinline__ uint32_t f2tf32(float x) {
    uint32_t u;
    asm("cvt.rna.tf32.f32 %0, %1;" : "=r"(u) : "f"(x));
    return u;
}

// swizzled float index into Xs[32][128]
__device__ __forceinline__ int xsw(int r, int k) {
    return r * 128 + (k & ~31) + ((k & 31) ^ ((r & 7) << 2));
}

// Block: 256 threads, 32-row x 32-col output tile.
// 8 warps = 2 row-groups(16) x 4 col-groups(8). Each warp: one m16n8k8 mma per k-step.
template <int FOUT>
__device__ __forceinline__ void gemm_tc_body(const float* __restrict__ X,
                                             const float* __restrict__ W,
                                             float* __restrict__ h, int n) {
    __shared__ float Xs[32 * 128];   // swizzled, 16 KB
    __shared__ float Ws[128 * 40];   // stride 40 -> bank = 8k+n (bijective), 20.5 KB
    const int tid = threadIdx.x;
    const int row0 = blockIdx.x * 32;
    const int colbase = blockIdx.y * 32;

    // X tile: 32 rows x 128 cols, float4 loads, cvt to tf32, swizzled store
    for (int i = tid; i < 32 * 32; i += 256) {
        int r = i >> 5, k4 = i & 31;
        int gr = row0 + r;
        float4 v = make_float4(0.f, 0.f, 0.f, 0.f);
        if (gr < n) v = *(const float4*)(X + (size_t)gr * FIN + k4 * 4);
        int k = k4 * 4;
        int sw = xsw(r, k);   // xor is multiple of 4 -> float4-aligned
        float4 t;
        t.x = __uint_as_float(f2tf32(v.x));
        t.y = __uint_as_float(f2tf32(v.y));
        t.z = __uint_as_float(f2tf32(v.z));
        t.w = __uint_as_float(f2tf32(v.w));
        *(float4*)(Xs + sw) = t;
    }
    // W tile: 128 k x 32 n
    for (int i = tid; i < 128 * 32; i += 256) {
        int k = i >> 5, nn = i & 31;
        float v = W[(size_t)k * FOUT + colbase + nn];
        Ws[k * 40 + nn] = __uint_as_float(f2tf32(v));
    }
    __syncthreads();

    const int warp = tid >> 5, lane = tid & 31;
    const int g = lane >> 2, tig = lane & 3;
    const int rg = warp & 1, cg = warp >> 1;
    const int ar = rg * 16 + g;       // A rows: ar, ar+8
    const int bn = cg * 8 + g;        // B col (n) for this lane

    float c0 = 0.f, c1 = 0.f, c2 = 0.f, c3 = 0.f;

    #pragma unroll
    for (int k0 = 0; k0 < 128; k0 += 8) {
        int kA0 = k0 + tig, kA1 = k0 + tig + 4;
        uint32_t a0 = __float_as_uint(Xs[xsw(ar, kA0)]);
        uint32_t a1 = __float_as_uint(Xs[xsw(ar + 8, kA0)]);
        uint32_t a2 = __float_as_uint(Xs[xsw(ar, kA1)]);
        uint32_t a3 = __float_as_uint(Xs[xsw(ar + 8, kA1)]);
        uint32_t b0 = __float_as_uint(Ws[kA0 * 40 + bn]);
        uint32_t b1 = __float_as_uint(Ws[kA1 * 40 + bn]);
        asm volatile(
            "mma.sync.aligned.m16n8k8.row.col.f32.tf32.tf32.f32 "
            "{%0,%1,%2,%3}, {%4,%5,%6,%7}, {%8,%9}, {%0,%1,%2,%3};"
            : "+f"(c0), "+f"(c1), "+f"(c2), "+f"(c3)
            : "r"(a0), "r"(a1), "r"(a2), "r"(a3), "r"(b0), "r"(b1));
    }

    // D layout: c0/c1 -> (row=g', col=2*tig, 2*tig+1); c2/c3 -> row+8
    int orow = row0 + rg * 16 + g;
    int ocol = colbase + cg * 8 + tig * 2;
    if (orow < n)
        *(float2*)(h + (size_t)orow * FOUT + ocol) = make_float2(c0, c1);
    if (orow + 8 < n)
        *(float2*)(h + (size_t)(orow + 8) * FOUT + ocol) = make_float2(c2, c3);
}

__global__ void __launch_bounds__(256) k_gemm1(const float* __restrict__ x,
                                               const float* __restrict__ W1, int n) {
    gemm_tc_body<F1>(x, W1, g_h1, n);
}
__global__ void __launch_bounds__(256) k_gemm2(const float* __restrict__ W2, int n) {
    gemm_tc_body<F2>(g_y1, W2, g_h2, n);
}

// ---------------- fused CSR aggregation (unchanged, measured fast) ----------------
__global__ void k_agg_relu(const float* __restrict__ b, int n) {
    int node = (blockIdx.x * blockDim.x + threadIdx.x) >> 5;
    int lane = threadIdx.x & 31;
    if (node >= n) return;
    float dv = g_dinv[node];

    float4 acc = *(const float4*)(g_h1 + (size_t)node * F1 + lane * 4);
    acc.x *= dv; acc.y *= dv; acc.z *= dv; acc.w *= dv;

    int beg = g_rowptr[node], end = g_rowptr[node + 1];
    int i = beg;
    for (; i + 4 <= end; i += 4) {
        int s0 = g_csrc[i], s1 = g_csrc[i + 1], s2 = g_csrc[i + 2], s3 = g_csrc[i + 3];
        float w0 = g_dinv[s0], w1 = g_dinv[s1], w2 = g_dinv[s2], w3 = g_dinv[s3];
        float4 v0 = *(const float4*)(g_h1 + (size_t)s0 * F1 + lane * 4);
        float4 v1 = *(const float4*)(g_h1 + (size_t)s1 * F1 + lane * 4);
        float4 v2 = *(const float4*)(g_h1 + (size_t)s2 * F1 + lane * 4);
        float4 v3 = *(const float4*)(g_h1 + (size_t)s3 * F1 + lane * 4);
        acc.x = fmaf(w0, v0.x, fmaf(w1, v1.x, fmaf(w2, v2.x, fmaf(w3, v3.x, acc.x))));
        acc.y = fmaf(w0, v0.y, fmaf(w1, v1.y, fmaf(w2, v2.y, fmaf(w3, v3.y, acc.y))));
        acc.z = fmaf(w0, v0.z, fmaf(w1, v1.z, fmaf(w2, v2.z, fmaf(w3, v3.z, acc.z))));
        acc.w = fmaf(w0, v0.w, fmaf(w1, v1.w, fmaf(w2, v2.w, fmaf(w3, v3.w, acc.w))));
    }
    for (; i < end; i++) {
        int s = g_csrc[i];
        float w = g_dinv[s];
        float4 v = *(const float4*)(g_h1 + (size_t)s * F1 + lane * 4);
        acc.x = fmaf(w, v.x, acc.x);
        acc.y = fmaf(w, v.y, acc.y);
        acc.z = fmaf(w, v.z, acc.z);
        acc.w = fmaf(w, v.w, acc.w);
    }

    float4 bb = *(const float4*)(b + lane * 4);
    float4 o;
    o.x = fmaxf(fmaf(acc.x, dv, bb.x), 0.f);
    o.y = fmaxf(fmaf(acc.y, dv, bb.y), 0.f);
    o.z = fmaxf(fmaf(acc.z, dv, bb.z), 0.f);
    o.w = fmaxf(fmaf(acc.w, dv, bb.w), 0.f);
    *(float4*)(g_y1 + (size_t)node * F1 + lane * 4) = o;
}

__global__ void k_agg_lsm(const float* __restrict__ b, float* __restrict__ out, int n) {
    int node = (blockIdx.x * blockDim.x + threadIdx.x) >> 5;
    int lane = threadIdx.x & 31;
    if (node >= n) return;
    float dv = g_dinv[node];

    float2 acc = *(const float2*)(g_h2 + (size_t)node * F2 + lane * 2);
    acc.x *= dv; acc.y *= dv;

    int beg = g_rowptr[node], end = g_rowptr[node + 1];
    int i = beg;
    for (; i + 4 <= end; i += 4) {
        int s0 = g_csrc[i], s1 = g_csrc[i + 1], s2 = g_csrc[i + 2], s3 = g_csrc[i + 3];
        float w0 = g_dinv[s0], w1 = g_dinv[s1], w2 = g_dinv[s2], w3 = g_dinv[s3];
        float2 v0 = *(const float2*)(g_h2 + (size_t)s0 * F2 + lane * 2);
        float2 v1 = *(const float2*)(g_h2 + (size_t)s1 * F2 + lane * 2);
        float2 v2 = *(const float2*)(g_h2 + (size_t)s2 * F2 + lane * 2);
        float2 v3 = *(const float2*)(g_h2 + (size_t)s3 * F2 + lane * 2);
        acc.x = fmaf(w0, v0.x, fmaf(w1, v1.x, fmaf(w2, v2.x, fmaf(w3, v3.x, acc.x))));
        acc.y = fmaf(w0, v0.y, fmaf(w1, v1.y, fmaf(w2, v2.y, fmaf(w3, v3.y, acc.y))));
    }
    for (; i < end; i++) {
        int s = g_csrc[i];
        float w = g_dinv[s];
        float2 v = *(const float2*)(g_h2 + (size_t)s * F2 + lane * 2);
        acc.x = fmaf(w, v.x, acc.x);
        acc.y = fmaf(w, v.y, acc.y);
    }

    float2 bb = *(const float2*)(b + lane * 2);
    float v0 = fmaf(acc.x, dv, bb.x);
    float v1 = fmaf(acc.y, dv, bb.y);
    float m = fmaxf(v0, v1);
    #pragma unroll
    for (int o = 16; o; o >>= 1) m = fmaxf(m, __shfl_xor_sync(0xffffffffu, m, o));
    float s = expf(v0 - m) + expf(v1 - m);
    #pragma unroll
    for (int o = 16; o; o >>= 1) s += __shfl_xor_sync(0xffffffffu, s, o);
    float lse = m + logf(s);
    float2 o2 = make_float2(v0 - lse, v1 - lse);
    *(float2*)(out + (size_t)node * F2 + lane * 2) = o2;
}

// ---------------- launch: single stream, straight-line ----------------
extern "C" void kernel_launch(void* const* d_in, const int* in_sizes, int n_in,
                              void* d_out, int out_size) {
    const float* x  = (const float*)d_in[0];
    const int* edge = (const int*)d_in[1];   // int32 [2, E]
    const float* W1 = (const float*)d_in[2];
    const float* b1 = (const float*)d_in[3];
    const float* W2 = (const float*)d_in[4];
    const float* b2 = (const float*)d_in[5];
    float* out = (float*)d_out;

    const int n = in_sizes[0] / FIN;  // 100000
    const int e = E_CONST;            // 640000
    const int T = 256;
    const int nblk = (n + SCAN_B - 1) / SCAN_B;
    const long long aggth = (long long)n * 32;
    const int aggblk = (int)((aggth + T - 1) / T);
    const dim3 grid1((n + 31) / 32, F1 / 32);
    const dim3 grid2((n + 31) / 32, F2 / 32);

    k_zero_cnt<<<(n + T - 1) / T, T>>>(n);
    k_count<<<(e + T - 1) / T, T>>>(edge, e);
    k_scan1<<<nblk, SCAN_B>>>(n);
    k_scan2<<<1, MAX_BLKS>>>(nblk);
    k_scan3<<<(n + T - 1) / T, T>>>(n);
    k_fill<<<(e + T - 1) / T, T>>>(edge, e);

    k_gemm1<<<grid1, T>>>(x, W1, n);
    k_agg_relu<<<aggblk, T>>>(b1, n);

    k_gemm2<<<grid2, T>>>(W2, n);
    k_agg_lsm<<<aggblk, T>>>(b2, out, n);
}

// round 17
// speedup vs baseline: 2.3648x; 1.1450x over previous
#include <cuda_runtime.h>
#include <cstdint>

#define N_MAX 100000
#define E_CONST 640000
#define FIN 128
#define F1 128
#define F2 64
#define SCAN_B 1024
#define MAX_BLKS 128

// ---------------- device-resident scratch ----------------
// RULE: referenced ONLY inside device code (host-taken addresses of __device__
// symbols resolve to the ATS host shadow on GB300 -> 3ms C2C penalty).
__device__ __align__(128) float g_dinv[N_MAX];
__device__ __align__(128) float g_h1[(size_t)N_MAX * F1];
__device__ __align__(128) float g_y1[(size_t)N_MAX * F1];
__device__ __align__(128) float g_h2[(size_t)N_MAX * F2];
__device__ int g_cnt[N_MAX];
__device__ int g_partial[N_MAX];
__device__ int g_bsum[MAX_BLKS];
__device__ int g_bpref[MAX_BLKS];
__device__ int g_rowptr[N_MAX + 1];
__device__ int g_woff[N_MAX];
__device__ int g_csrc[E_CONST];

// ---------------- CSR build ----------------
__global__ void k_zero_cnt(int n) {
    int i = blockIdx.x * blockDim.x + threadIdx.x;
    if (i < n) g_cnt[i] = 0;
}

__global__ void k_count(const int* __restrict__ edge, int e) {
    int i = blockIdx.x * blockDim.x + threadIdx.x;
    if (i < e) atomicAdd(&g_cnt[edge[e + i]], 1);  // dst
}

__global__ void k_scan1(int n) {
    __shared__ int sm[SCAN_B];
    int t = threadIdx.x;
    int i = blockIdx.x * SCAN_B + t;
    sm[t] = (i < n) ? g_cnt[i] : 0;
    __syncthreads();
    for (int off = 1; off < SCAN_B; off <<= 1) {
        int x = sm[t];
        if (t >= off) x += sm[t - off];
        __syncthreads();
        sm[t] = x;
        __syncthreads();
    }
    if (i < n) g_partial[i] = sm[t];
    if (t == SCAN_B - 1) g_bsum[blockIdx.x] = sm[t];
}

__global__ void k_scan2(int nblk) {
    __shared__ int sm[MAX_BLKS];
    int t = threadIdx.x;
    sm[t] = (t < nblk) ? g_bsum[t] : 0;
    __syncthreads();
    for (int off = 1; off < MAX_BLKS; off <<= 1) {
        int x = sm[t];
        if (t >= off) x += sm[t - off];
        __syncthreads();
        sm[t] = x;
        __syncthreads();
    }
    g_bpref[t] = sm[t];
}

__global__ void k_scan3(int n) {
    int i = blockIdx.x * blockDim.x + threadIdx.x;
    if (i < n) {
        int c = g_cnt[i];
        int b = i >> 10;
        int off = (b > 0) ? g_bpref[b - 1] : 0;
        int incl = g_partial[i] + off;
        g_rowptr[i + 1] = incl;
        g_woff[i] = incl - c;
        g_dinv[i] = rsqrtf(1.0f + (float)c);
    }
    if (i == 0) g_rowptr[0] = 0;
}

__global__ void k_fill(const int* __restrict__ edge, int e) {
    int i = blockIdx.x * blockDim.x + threadIdx.x;
    if (i < e) {
        int d = edge[e + i];
        int pos = atomicAdd(&g_woff[d], 1);
        g_csrc[pos] = edge[i];
    }
}

// ---------------- tf32 tensor-core GEMM v2 (32x64 tile, 2 mma/warp/k-step) -------
__device__ __forceinline__ uint32_t f2tf32(float x) {
    uint32_t u;
    asm("cvt.rna.tf32.f32 %0, %1;" : "=r"(u) : "f"(x));
    return u;
}

// swizzled float index into Xs[32][128]
__device__ __forceinline__ int xsw(int r, int k) {
    return r * 128 + (k & ~31) + ((k & 31) ^ ((r & 7) << 2));
}
// swizzled float index into Ws[128][64] (k-major)
__device__ __forceinline__ int wsw(int k, int nn) {
    return k * 64 + (nn & 32) + ((nn & 31) ^ ((k & 7) << 2));
}

// Block: 256 threads, 32-row x 64-col tile. 8 warps = 2 rowgroups x 4 colgroups(16).
// Each warp: m16n16 per k-step = 2 mmas sharing the A fragment.
template <int FOUT>
__device__ __forceinline__ void gemm_tc_body(const float* __restrict__ X,
                                             const float* __restrict__ W,
                                             float* __restrict__ h, int n) {
    __shared__ float Xs[32 * 128];   // 16 KB, swizzled
    __shared__ float Ws[128 * 64];   // 32 KB, swizzled
    const int tid = threadIdx.x;
    const int row0 = blockIdx.x * 32;
    const int colbase = blockIdx.y * 64;

    // X tile: 32 rows x 128 k (float4 + tf32 cvt + swizzle)
    for (int i = tid; i < 32 * 32; i += 256) {
        int r = i >> 5, k4 = i & 31;
        int gr = row0 + r;
        float4 v = make_float4(0.f, 0.f, 0.f, 0.f);
        if (gr < n) v = *(const float4*)(X + (size_t)gr * FIN + k4 * 4);
        float4 t;
        t.x = __uint_as_float(f2tf32(v.x));
        t.y = __uint_as_float(f2tf32(v.y));
        t.z = __uint_as_float(f2tf32(v.z));
        t.w = __uint_as_float(f2tf32(v.w));
        *(float4*)(Xs + xsw(r, k4 * 4)) = t;
    }
    // W tile: 128 k x 64 n (scalar coalesced reads, conflict-free swizzled stores)
    for (int i = tid; i < 128 * 64; i += 256) {
        int k = i >> 6, nn = i & 63;
        float v = W[(size_t)k * FOUT + colbase + nn];
        Ws[wsw(k, nn)] = __uint_as_float(f2tf32(v));
    }
    __syncthreads();

    const int warp = tid >> 5, lane = tid & 31;
    const int g = lane >> 2, tig = lane & 3;
    const int rg = warp & 1, cg = warp >> 1;
    const int ar = rg * 16 + g;            // A rows: ar, ar+8
    const int bn1 = cg * 16 + g;           // B col for mma1
    const int bn2 = bn1 + 8;               // B col for mma2

    float c0[4] = {0.f, 0.f, 0.f, 0.f};
    float c1[4] = {0.f, 0.f, 0.f, 0.f};

    #pragma unroll
    for (int k0 = 0; k0 < 128; k0 += 8) {
        int kA0 = k0 + tig, kA1 = kA0 + 4;
        uint32_t a0 = __float_as_uint(Xs[xsw(ar, kA0)]);
        uint32_t a1 = __float_as_uint(Xs[xsw(ar + 8, kA0)]);
        uint32_t a2 = __float_as_uint(Xs[xsw(ar, kA1)]);
        uint32_t a3 = __float_as_uint(Xs[xsw(ar + 8, kA1)]);
        uint32_t p0 = __float_as_uint(Ws[wsw(kA0, bn1)]);
        uint32_t p1 = __float_as_uint(Ws[wsw(kA1, bn1)]);
        uint32_t q0 = __float_as_uint(Ws[wsw(kA0, bn2)]);
        uint32_t q1 = __float_as_uint(Ws[wsw(kA1, bn2)]);
        asm volatile(
            "mma.sync.aligned.m16n8k8.row.col.f32.tf32.tf32.f32 "
            "{%0,%1,%2,%3}, {%4,%5,%6,%7}, {%8,%9}, {%0,%1,%2,%3};"
            : "+f"(c0[0]), "+f"(c0[1]), "+f"(c0[2]), "+f"(c0[3])
            : "r"(a0), "r"(a1), "r"(a2), "r"(a3), "r"(p0), "r"(p1));
        asm volatile(
            "mma.sync.aligned.m16n8k8.row.col.f32.tf32.tf32.f32 "
            "{%0,%1,%2,%3}, {%4,%5,%6,%7}, {%8,%9}, {%0,%1,%2,%3};"
            : "+f"(c1[0]), "+f"(c1[1]), "+f"(c1[2]), "+f"(c1[3])
            : "r"(a0), "r"(a1), "r"(a2), "r"(a3), "r"(q0), "r"(q1));
    }

    int orow = row0 + rg * 16 + g;
    int ocol = colbase + cg * 16 + tig * 2;
    if (orow < n) {
        *(float2*)(h + (size_t)orow * FOUT + ocol)     = make_float2(c0[0], c0[1]);
        *(float2*)(h + (size_t)orow * FOUT + ocol + 8) = make_float2(c1[0], c1[1]);
    }
    if (orow + 8 < n) {
        *(float2*)(h + (size_t)(orow + 8) * FOUT + ocol)     = make_float2(c0[2], c0[3]);
        *(float2*)(h + (size_t)(orow + 8) * FOUT + ocol + 8) = make_float2(c1[2], c1[3]);
    }
}

__global__ void __launch_bounds__(256) k_gemm1(const float* __restrict__ x,
                                               const float* __restrict__ W1, int n) {
    gemm_tc_body<F1>(x, W1, g_h1, n);
}
__global__ void __launch_bounds__(256) k_gemm2(const float* __restrict__ W2, int n) {
    gemm_tc_body<F2>(g_y1, W2, g_h2, n);
}

// ---------------- fused CSR aggregation (unchanged, measured fast) ----------------
__global__ void k_agg_relu(const float* __restrict__ b, int n) {
    int node = (blockIdx.x * blockDim.x + threadIdx.x) >> 5;
    int lane = threadIdx.x & 31;
    if (node >= n) return;
    float dv = g_dinv[node];

    float4 acc = *(const float4*)(g_h1 + (size_t)node * F1 + lane * 4);
    acc.x *= dv; acc.y *= dv; acc.z *= dv; acc.w *= dv;

    int beg = g_rowptr[node], end = g_rowptr[node + 1];
    int i = beg;
    for (; i + 4 <= end; i += 4) {
        int s0 = g_csrc[i], s1 = g_csrc[i + 1], s2 = g_csrc[i + 2], s3 = g_csrc[i + 3];
        float w0 = g_dinv[s0], w1 = g_dinv[s1], w2 = g_dinv[s2], w3 = g_dinv[s3];
        float4 v0 = *(const float4*)(g_h1 + (size_t)s0 * F1 + lane * 4);
        float4 v1 = *(const float4*)(g_h1 + (size_t)s1 * F1 + lane * 4);
        float4 v2 = *(const float4*)(g_h1 + (size_t)s2 * F1 + lane * 4);
        float4 v3 = *(const float4*)(g_h1 + (size_t)s3 * F1 + lane * 4);
        acc.x = fmaf(w0, v0.x, fmaf(w1, v1.x, fmaf(w2, v2.x, fmaf(w3, v3.x, acc.x))));
        acc.y = fmaf(w0, v0.y, fmaf(w1, v1.y, fmaf(w2, v2.y, fmaf(w3, v3.y, acc.y))));
        acc.z = fmaf(w0, v0.z, fmaf(w1, v1.z, fmaf(w2, v2.z, fmaf(w3, v3.z, acc.z))));
        acc.w = fmaf(w0, v0.w, fmaf(w1, v1.w, fmaf(w2, v2.w, fmaf(w3, v3.w, acc.w))));
    }
    for (; i < end; i++) {
        int s = g_csrc[i];
        float w = g_dinv[s];
        float4 v = *(const float4*)(g_h1 + (size_t)s * F1 + lane * 4);
        acc.x = fmaf(w, v.x, acc.x);
        acc.y = fmaf(w, v.y, acc.y);
        acc.z = fmaf(w, v.z, acc.z);
        acc.w = fmaf(w, v.w, acc.w);
    }

    float4 bb = *(const float4*)(b + lane * 4);
    float4 o;
    o.x = fmaxf(fmaf(acc.x, dv, bb.x), 0.f);
    o.y = fmaxf(fmaf(acc.y, dv, bb.y), 0.f);
    o.z = fmaxf(fmaf(acc.z, dv, bb.z), 0.f);
    o.w = fmaxf(fmaf(acc.w, dv, bb.w), 0.f);
    *(float4*)(g_y1 + (size_t)node * F1 + lane * 4) = o;
}

__global__ void k_agg_lsm(const float* __restrict__ b, float* __restrict__ out, int n) {
    int node = (blockIdx.x * blockDim.x + threadIdx.x) >> 5;
    int lane = threadIdx.x & 31;
    if (node >= n) return;
    float dv = g_dinv[node];

    float2 acc = *(const float2*)(g_h2 + (size_t)node * F2 + lane * 2);
    acc.x *= dv; acc.y *= dv;

    int beg = g_rowptr[node], end = g_rowptr[node + 1];
    int i = beg;
    for (; i + 4 <= end; i += 4) {
        int s0 = g_csrc[i], s1 = g_csrc[i + 1], s2 = g_csrc[i + 2], s3 = g_csrc[i + 3];
        float w0 = g_dinv[s0], w1 = g_dinv[s1], w2 = g_dinv[s2], w3 = g_dinv[s3];
        float2 v0 = *(const float2*)(g_h2 + (size_t)s0 * F2 + lane * 2);
        float2 v1 = *(const float2*)(g_h2 + (size_t)s1 * F2 + lane * 2);
        float2 v2 = *(const float2*)(g_h2 + (size_t)s2 * F2 + lane * 2);
        float2 v3 = *(const float2*)(g_h2 + (size_t)s3 * F2 + lane * 2);
        acc.x = fmaf(w0, v0.x, fmaf(w1, v1.x, fmaf(w2, v2.x, fmaf(w3, v3.x, acc.x))));
        acc.y = fmaf(w0, v0.y, fmaf(w1, v1.y, fmaf(w2, v2.y, fmaf(w3, v3.y, acc.y))));
    }
    for (; i < end; i++) {
        int s = g_csrc[i];
        float w = g_dinv[s];
        float2 v = *(const float2*)(g_h2 + (size_t)s * F2 + lane * 2);
        acc.x = fmaf(w, v.x, acc.x);
        acc.y = fmaf(w, v.y, acc.y);
    }

    float2 bb = *(const float2*)(b + lane * 2);
    float v0 = fmaf(acc.x, dv, bb.x);
    float v1 = fmaf(acc.y, dv, bb.y);
    float m = fmaxf(v0, v1);
    #pragma unroll
    for (int o = 16; o; o >>= 1) m = fmaxf(m, __shfl_xor_sync(0xffffffffu, m, o));
    float s = expf(v0 - m) + expf(v1 - m);
    #pragma unroll
    for (int o = 16; o; o >>= 1) s += __shfl_xor_sync(0xffffffffu, s, o);
    float lse = m + logf(s);
    float2 o2 = make_float2(v0 - lse, v1 - lse);
    *(float2*)(out + (size_t)node * F2 + lane * 2) = o2;
}

// ---------------- launch: single stream; gemm1 hoisted to index 3 for ncu -------
extern "C" void kernel_launch(void* const* d_in, const int* in_sizes, int n_in,
                              void* d_out, int out_size) {
    const float* x  = (const float*)d_in[0];
    const int* edge = (const int*)d_in[1];   // int32 [2, E]
    const float* W1 = (const float*)d_in[2];
    const float* b1 = (const float*)d_in[3];
    const float* W2 = (const float*)d_in[4];
    const float* b2 = (const float*)d_in[5];
    float* out = (float*)d_out;

    const int n = in_sizes[0] / FIN;  // 100000
    const int e = E_CONST;            // 640000
    const int T = 256;
    const int nblk = (n + SCAN_B - 1) / SCAN_B;
    const long long aggth = (long long)n * 32;
    const int aggblk = (int)((aggth + T - 1) / T);
    const dim3 grid1((n + 31) / 32, F1 / 64);   // (3125, 2)
    const dim3 grid2((n + 31) / 32, F2 / 64);   // (3125, 1)

    k_zero_cnt<<<(n + T - 1) / T, T>>>(n);      // 0
    k_count<<<(e + T - 1) / T, T>>>(edge, e);   // 1
    k_scan1<<<nblk, SCAN_B>>>(n);               // 2
    k_gemm1<<<grid1, T>>>(x, W1, n);            // 3  <- ncu target (needs only x,W1)
    k_scan2<<<1, MAX_BLKS>>>(nblk);             // 4
    k_scan3<<<(n + T - 1) / T, T>>>(n);         // 5
    k_fill<<<(e + T - 1) / T, T>>>(edge, e);    // 6
    k_agg_relu<<<aggblk, T>>>(b1, n);           // 7
    k_gemm2<<<grid2, T>>>(W2, n);               // 8
    k_agg_lsm<<<aggblk, T>>>(b2, out, n);       // 9
}